// round 7
// baseline (speedup 1.0000x reference)
#include <cuda_runtime.h>
#include <cuda_bf16.h>
#include <cstdint>

// Problem dims
#define BB   256
#define TT   512
#define EMB  128
#define HID  256
#define NCLS 32000

#define NBLK   148      // persistent grid, 1 block/SM
#define NCHUNK 500      // 32000 / 64
#define WPAD   132      // bf16x2 words per Wsh row (conflict-free ldmatrix)

// Dynamic smem layout:
//   [0,      131072) : A image — H fragments [m_tile(16)][ks(16)][lane(32)] uint4
//   [131072, 164864) : Wsh buf0  (64 rows x WPAD words)
//   [164864, 198656) : Wsh buf1
//   phase-1 overlays Esh/Hsh/toks on the Wsh region (disjoint lifetime)
#define SMEM_A     0
#define SMEM_W0    131072
#define SMEM_WBUF  33792
#define SMEM_BYTES (131072 + 2 * SMEM_WBUF)

// H pre-swizzled into mma A-fragment order (gmem master copy).
__device__ uint4 g_h0p[16 * 16 * 32];   // 128 KB
// Monotonic ticket barrier (graph-replay safe: never reset).
__device__ unsigned int g_bar;

__device__ __forceinline__ void mma_bf16(float c[4], uint32_t a0, uint32_t a1,
                                         uint32_t a2, uint32_t a3,
                                         uint32_t b0, uint32_t b1)
{
    asm volatile(
        "mma.sync.aligned.m16n8k16.row.col.f32.bf16.bf16.f32 "
        "{%0,%1,%2,%3}, {%4,%5,%6,%7}, {%8,%9}, {%0,%1,%2,%3};"
        : "+f"(c[0]), "+f"(c[1]), "+f"(c[2]), "+f"(c[3])
        : "r"(a0), "r"(a1), "r"(a2), "r"(a3), "r"(b0), "r"(b1));
}

__device__ __forceinline__ void ldsm_x4(uint32_t& r0, uint32_t& r1,
                                        uint32_t& r2, uint32_t& r3, uint32_t saddr)
{
    asm volatile("ldmatrix.sync.aligned.m8n8.x4.shared.b16 {%0,%1,%2,%3}, [%4];"
                 : "=r"(r0), "=r"(r1), "=r"(r2), "=r"(r3) : "r"(saddr));
}

__device__ __forceinline__ void cp_async16(uint32_t saddr, const void* gaddr)
{
    asm volatile("cp.async.cg.shared.global [%0], [%1], 16;"
                 :: "r"(saddr), "l"(gaddr));
}

__global__ void __launch_bounds__(512) fused_kernel(
    const int* __restrict__ X, const float* __restrict__ C_table,
    const float* __restrict__ U_i, const float* __restrict__ b_i,
    const float* __restrict__ U_c, const float* __restrict__ b_c,
    const float* __restrict__ U_o, const float* __restrict__ b_o,
    const float* __restrict__ W, const float* __restrict__ b_out,
    float* __restrict__ out)
{
    extern __shared__ char smem[];
    uint32_t* Wsh0 = reinterpret_cast<uint32_t*>(smem + SMEM_W0);
    // Phase-1 overlays on the Wsh region:
    float (*Esh)[4][EMB] = reinterpret_cast<float(*)[4][EMB]>(smem + SMEM_W0);
    float (*Hsh)[4][64]  = reinterpret_cast<float(*)[4][64]>(smem + SMEM_W0 + 8192);
    int   (*toks)[4]     = reinterpret_cast<int(*)[4]>(smem + SMEM_W0 + 8192 + 4096);

    const int tid  = threadIdx.x;
    const int bid  = blockIdx.x;
    const uint32_t smem_base = (uint32_t)__cvta_generic_to_shared(smem);

    // ===================== Phase 1: layer-0 LSTM + fragment pack ==========
    {
        const int grp  = tid >> 7;                 // 0..3
        const int gtid = tid & 127;
        const int vb   = bid + NBLK * grp;
        const bool act = (vb < 256);

        int row_block = vb & 63;
        int h_block   = vb >> 6;
        int b0 = row_block * 4;
        int hb = h_block * 64;

        if (act && gtid < 4) toks[grp][gtid] = X[(b0 + gtid) * TT + (TT - 1)];
        __syncthreads();
        if (act) {
#pragma unroll
            for (int j = 0; j < 4; j++) {
                int idx = gtid + 128 * j;
                int r = idx >> 7, e = idx & 127;
                Esh[grp][r][e] = C_table[toks[grp][r] * EMB + e];
            }
        }
        __syncthreads();

        if (act) {
            const int h_local = gtid & 63;
            const int rp      = gtid >> 6;
            const int h       = hb + h_local;
            const int r0 = rp * 2, r1 = rp * 2 + 1;

            float ai0 = 0.f, ai1 = 0.f, ac0 = 0.f, ac1 = 0.f, ao0 = 0.f, ao1 = 0.f;
#pragma unroll 8
            for (int e = 0; e < EMB; e++) {
                float ui = U_i[e * HID + h];
                float uc = U_c[e * HID + h];
                float uo = U_o[e * HID + h];
                float e0 = Esh[grp][r0][e], e1 = Esh[grp][r1][e];
                ai0 = fmaf(e0, ui, ai0); ai1 = fmaf(e1, ui, ai1);
                ac0 = fmaf(e0, uc, ac0); ac1 = fmaf(e1, uc, ac1);
                ao0 = fmaf(e0, uo, ao0); ao1 = fmaf(e1, uo, ao1);
            }
            const float bi = b_i[h], bc = b_c[h], bo = b_o[h];
            float i0 = 1.f / (1.f + expf(-(ai0 + bi)));
            float g0 = tanhf(ac0 + bc);
            float o0 = 1.f / (1.f + expf(-(ao0 + bo)));
            Hsh[grp][r0][h_local] = o0 * tanhf(i0 * g0);
            float i1 = 1.f / (1.f + expf(-(ai1 + bi)));
            float g1 = tanhf(ac1 + bc);
            float o1 = 1.f / (1.f + expf(-(ao1 + bo)));
            Hsh[grp][r1][h_local] = o1 * tanhf(i1 * g1);
        }
        __syncthreads();

        if (act) {
            uint32_t* Hw = reinterpret_cast<uint32_t*>(g_h0p);
            int r  = gtid >> 5;
            int wl = gtid & 31;
            int w  = h_block * 32 + wl;
            int gr = b0 + r;
            int m_tile = gr >> 4;
            int local  = gr & 15;
            int g      = local & 7;
            int comp_r = local >> 3;
            int ks     = w >> 3;
            int ww     = w & 7;
            int tg     = ww & 3;
            int comp_k = (ww >> 2) << 1;
            int lane   = g * 4 + tg;
            __nv_bfloat162 bv =
                __floats2bfloat162_rn(Hsh[grp][r][2 * wl], Hsh[grp][r][2 * wl + 1]);
            Hw[((((m_tile * 16) + ks) * 32 + lane) << 2) + (comp_r + comp_k)] =
                *reinterpret_cast<uint32_t*>(&bv);
        }
        __syncthreads();   // Wsh region free for reuse
    }

    const int nch = (NCHUNK - bid + NBLK - 1) / NBLK;   // 3 or 4 chunks

    // ------ Prefetch chunk-0 W into registers (covers barrier wait) -------
    float4 wreg[8];
    {
        const float4* W4 =
            reinterpret_cast<const float4*>(W + (size_t)bid * 64 * HID);
#pragma unroll
        for (int j = 0; j < 8; j++) wreg[j] = W4[tid + 512 * j];
    }

    // ===================== Global barrier (release/acquire) ===============
    __threadfence();
    if (tid == 0) {
        unsigned int t = atomicAdd(&g_bar, 1u);
        unsigned int target = (t / NBLK + 1u) * NBLK;
        while (*((volatile unsigned int*)&g_bar) < target) { __nanosleep(64); }
    }
    __syncthreads();
    __threadfence();

    // ------ Pull full A image into smem (linear cp.async, 256B/thread) ----
#pragma unroll
    for (int j = 0; j < 16; j++) {
        int idx = tid + 512 * j;
        cp_async16(smem_base + SMEM_A + (uint32_t)idx * 16u,
                   reinterpret_cast<const char*>(g_h0p) + idx * 16);
    }
    asm volatile("cp.async.commit_group;");
    asm volatile("cp.async.wait_group 0;");

    // ===================== Phase 2: logits = H @ W^T + b ==================
    const int warp = tid >> 5;   // m-tile 0..15
    const int lane = tid & 31;
    const int g  = lane >> 2;
    const int tg = lane & 3;

    const int lmRow  = ((lane >> 4) * 8) + (lane & 7);
    const int lmHalf = ((lane >> 3) & 1) * 4;
    const uint32_t lmOff = (uint32_t)(lmRow * WPAD + lmHalf) * 4u;
    const uint32_t ABase = smem_base + SMEM_A + (uint32_t)(warp * 16 * 32 + lane) * 16u;

#pragma unroll 1
    for (int i = 0; i < nch; i++) {
        const int buf = i & 1;
        uint32_t* Wsh = Wsh0 + buf * (SMEM_WBUF / 4);

        // Convert prefetched W_i regs -> bf16 Wsh[buf]
#pragma unroll
        for (int j = 0; j < 8; j++) {
            int idx  = tid + 512 * j;
            int row  = idx >> 6;
            int col2 = (idx & 63) * 2;
            __nv_bfloat162 lo = __floats2bfloat162_rn(wreg[j].x, wreg[j].y);
            __nv_bfloat162 hi = __floats2bfloat162_rn(wreg[j].z, wreg[j].w);
            Wsh[row * WPAD + col2]     = *reinterpret_cast<uint32_t*>(&lo);
            Wsh[row * WPAD + col2 + 1] = *reinterpret_cast<uint32_t*>(&hi);
        }

        // Prefetch W_{i+1} (overlaps this chunk's MMA loop)
        if (i + 1 < nch) {
            const float4* W4 = reinterpret_cast<const float4*>(
                W + (size_t)(bid + NBLK * (i + 1)) * 64 * HID);
#pragma unroll
            for (int j = 0; j < 8; j++) wreg[j] = W4[tid + 512 * j];
        }
        __syncthreads();

        const uint32_t WB = smem_base + SMEM_W0 + (uint32_t)buf * SMEM_WBUF + lmOff;

        float c[8][4];
#pragma unroll
        for (int nf = 0; nf < 8; nf++)
#pragma unroll
            for (int q = 0; q < 4; q++) c[nf][q] = 0.f;

#pragma unroll 4
        for (int ks = 0; ks < 16; ks++) {
            uint4 va = *reinterpret_cast<const uint4*>(smem + SMEM_A +
                        (size_t)(warp * 16 + ks) * 512 + lane * 16);
            const uint32_t kwb = (uint32_t)(ks * 8) * 4u;
#pragma unroll
            for (int nfp = 0; nfp < 4; nfp++) {
                uint32_t b0r, b1r, b2r, b3r;
                ldsm_x4(b0r, b1r, b2r, b3r,
                        WB + (uint32_t)(nfp * 16 * WPAD) * 4u + kwb);
                mma_bf16(c[2 * nfp],     va.x, va.y, va.z, va.w, b0r, b1r);
                mma_bf16(c[2 * nfp + 1], va.x, va.y, va.z, va.w, b2r, b3r);
            }
        }

        const int n_base = (bid + NBLK * i) * 64;
        const int r0 = warp * 16 + g;
#pragma unroll
        for (int nf = 0; nf < 8; nf++) {
            const int n = n_base + nf * 8 + tg * 2;
            const float2 bo = *reinterpret_cast<const float2*>(b_out + n);
            float2 v0 = make_float2(c[nf][0] + bo.x, c[nf][1] + bo.y);
            float2 v1 = make_float2(c[nf][2] + bo.x, c[nf][3] + bo.y);
            *reinterpret_cast<float2*>(out + (size_t)(r0    ) * NCLS + n) = v0;
            *reinterpret_cast<float2*>(out + (size_t)(r0 + 8) * NCLS + n) = v1;
        }
        // No sync needed here: next iteration writes the OTHER Wsh buffer;
        // the per-iteration __syncthreads() above keeps buffers consistent.
    }
}

// ---------------------------------------------------------------------------
extern "C" void kernel_launch(void* const* d_in, const int* in_sizes, int n_in,
                              void* d_out, int out_size)
{
    const int*   X       = (const int*)  d_in[0];
    const float* C_table = (const float*)d_in[1];
    const float* U_i     = (const float*)d_in[2];
    const float* b_i     = (const float*)d_in[4];
    const float* U_c     = (const float*)d_in[8];
    const float* b_c     = (const float*)d_in[10];
    const float* U_o     = (const float*)d_in[11];
    const float* b_o     = (const float*)d_in[13];
    const float* W_w     = (const float*)d_in[26];
    const float* b_out   = (const float*)d_in[27];
    float* out = (float*)d_out;

    cudaFuncSetAttribute(fused_kernel,
                         cudaFuncAttributeMaxDynamicSharedMemorySize, SMEM_BYTES);

    fused_kernel<<<NBLK, 512, SMEM_BYTES>>>(X, C_table, U_i, b_i, U_c, b_c,
                                            U_o, b_o, W_w, b_out, out);
}

// round 8
// speedup vs baseline: 1.1034x; 1.1034x over previous
#include <cuda_runtime.h>
#include <cuda_bf16.h>
#include <cstdint>

// Problem dims
#define BB   256
#define TT   512
#define EMB  128
#define HID  256
#define NCLS 32000

#define NBLK   148       // persistent grid, 1 block/SM
#define NCHUNK 1000      // 32000 / 32
#define WPITCH 272       // bytes per Wf8 smem row (17x16B -> conflict-free ldmatrix)
#define WBUF   (32 * WPITCH)   // 8704 B per chunk buffer

// Dynamic smem:
//   [0,     65536) : A image — H e4m3 fragments [m_tile(16)][ks(8)][lane(32)] uint4
//   [65536, +WBUF) : Wf8 buf0 ; [+WBUF, +2*WBUF) : Wf8 buf1
//   phase-1 overlays Esh/Hsh/toks on the Wf8 region
#define SMEM_A     0
#define SMEM_W0    65536
#define SMEM_BYTES (65536 + 2 * WBUF)

#define SCL  64.0f                 // quantization scale for A and W
#define INVS (1.0f / 4096.0f)      // 1/(SCL*SCL)

__device__ uint4 g_h0p[16 * 8 * 32];   // 64 KB A-fragment master image
__device__ unsigned int g_bar;         // monotonic ticket barrier

// --------------------------- helpers ---------------------------------------
__device__ __forceinline__ uint32_t pack_e4m3(float f0, float f1, float f2, float f3)
{
    uint32_t r;
    asm("{\n\t.reg .b16 lo, hi;\n\t"
        "cvt.rn.satfinite.e4m3x2.f32 lo, %2, %1;\n\t"
        "cvt.rn.satfinite.e4m3x2.f32 hi, %4, %3;\n\t"
        "mov.b32 %0, {lo, hi};\n\t}"
        : "=r"(r) : "f"(f0), "f"(f1), "f"(f2), "f"(f3));
    return r;
}

__device__ __forceinline__ void mma_e4m3(float c[4], uint32_t a0, uint32_t a1,
                                         uint32_t a2, uint32_t a3,
                                         uint32_t b0, uint32_t b1)
{
    asm volatile(
        "mma.sync.aligned.m16n8k32.row.col.f32.e4m3.e4m3.f32 "
        "{%0,%1,%2,%3}, {%4,%5,%6,%7}, {%8,%9}, {%0,%1,%2,%3};"
        : "+f"(c[0]), "+f"(c[1]), "+f"(c[2]), "+f"(c[3])
        : "r"(a0), "r"(a1), "r"(a2), "r"(a3), "r"(b0), "r"(b1));
}

__device__ __forceinline__ void ldsm_x4(uint32_t& r0, uint32_t& r1,
                                        uint32_t& r2, uint32_t& r3, uint32_t saddr)
{
    asm volatile("ldmatrix.sync.aligned.m8n8.x4.shared.b16 {%0,%1,%2,%3}, [%4];"
                 : "=r"(r0), "=r"(r1), "=r"(r2), "=r"(r3) : "r"(saddr));
}

__device__ __forceinline__ void cp_async16(uint32_t saddr, const void* gaddr)
{
    asm volatile("cp.async.cg.shared.global [%0], [%1], 16;"
                 :: "r"(saddr), "l"(gaddr));
}

// ---------------------------------------------------------------------------
__global__ void __launch_bounds__(512) fused_kernel(
    const int* __restrict__ X, const float* __restrict__ C_table,
    const float* __restrict__ U_i, const float* __restrict__ b_i,
    const float* __restrict__ U_c, const float* __restrict__ b_c,
    const float* __restrict__ U_o, const float* __restrict__ b_o,
    const float* __restrict__ W, const float* __restrict__ b_out,
    float* __restrict__ out)
{
    extern __shared__ char smem[];
    // Phase-1 overlays on the Wf8 region:
    float (*Esh)[EMB] = reinterpret_cast<float(*)[EMB]>(smem + SMEM_W0);
    float (*Hsh)[HID] = reinterpret_cast<float(*)[HID]>(smem + SMEM_W0 + 1024);
    int*   toks       = reinterpret_cast<int*>(smem + SMEM_W0 + 1024 + 2048);

    const int tid = threadIdx.x;
    const int bid = blockIdx.x;
    const uint32_t smem_base = (uint32_t)__cvta_generic_to_shared(smem);

    // ===================== Phase 1: layer-0 LSTM + fragment pack ==========
    // 128 active blocks; block b handles batch rows 2b, 2b+1 (all 256 h).
    const bool act = (bid < 128);
    if (act && tid < 2) toks[tid] = X[(bid * 2 + tid) * TT + (TT - 1)];
    __syncthreads();
    if (act && tid < 256) {
        int r = tid >> 7, e = tid & 127;
        Esh[r][e] = C_table[toks[r] * EMB + e];
    }
    __syncthreads();

    if (act) {
        const int r = tid >> 8;        // 0..1
        const int h = tid & 255;
        float ai = 0.f, ac = 0.f, ao = 0.f;
#pragma unroll 8
        for (int e = 0; e < EMB; e++) {
            float ev = Esh[r][e];
            ai = fmaf(ev, U_i[e * HID + h], ai);
            ac = fmaf(ev, U_c[e * HID + h], ac);
            ao = fmaf(ev, U_o[e * HID + h], ao);
        }
        float i0 = 1.f / (1.f + expf(-(ai + b_i[h])));
        float g0 = tanhf(ac + b_c[h]);
        float o0 = 1.f / (1.f + expf(-(ao + b_o[h])));
        Hsh[r][h] = o0 * tanhf(i0 * g0);
    }
    __syncthreads();

    if (act && tid < 128) {
        // Pack 4 consecutive h (k dim) into one e4m3 word, fragment layout.
        uint32_t* Hw = reinterpret_cast<uint32_t*>(g_h0p);
        int r  = tid >> 6;             // 0..1
        int q  = tid & 63;             // quad index, k0 = 4q
        int k0 = q * 4;
        int gr = bid * 2 + r;
        int m_tile = gr >> 4;
        int local  = gr & 15;
        int g      = local & 7;
        int comp_r = local >> 3;
        int ks     = q >> 3;
        int tg     = q & 3;
        int comp_k = ((q >> 2) & 1) << 1;
        int lane   = g * 4 + tg;
        uint32_t v = pack_e4m3(Hsh[r][k0] * SCL, Hsh[r][k0 + 1] * SCL,
                               Hsh[r][k0 + 2] * SCL, Hsh[r][k0 + 3] * SCL);
        Hw[(((m_tile * 8 + ks) * 32 + lane) << 2) + (comp_r + comp_k)] = v;
    }
    __syncthreads();   // Wf8 region free for reuse

    const int nch = (NCHUNK - bid + NBLK - 1) / NBLK;   // 6 or 7 chunks

    // ------ Prefetch chunk-0 W into registers (covers barrier wait) -------
    // Thread t: class n_loc = t>>4, k-segment (t&15)*16 -> 16 floats.
    float4 wreg[4];
    {
        const float4* W4 = reinterpret_cast<const float4*>(
            W + (size_t)(bid * 32 + (tid >> 4)) * HID + (tid & 15) * 16);
#pragma unroll
        for (int j = 0; j < 4; j++) wreg[j] = W4[j];
    }

    // ===================== Global barrier (release/acquire) ===============
    __threadfence();
    if (tid == 0) {
        unsigned int t = atomicAdd(&g_bar, 1u);
        unsigned int target = (t / NBLK + 1u) * NBLK;
        while (*((volatile unsigned int*)&g_bar) < target) { __nanosleep(64); }
    }
    __syncthreads();
    __threadfence();

    // ------ Pull A image into smem (linear cp.async, 128B/thread) ---------
#pragma unroll
    for (int j = 0; j < 8; j++) {
        int idx = tid + 512 * j;       // 0..4095 x 16B = 64KB
        cp_async16(smem_base + SMEM_A + (uint32_t)idx * 16u,
                   reinterpret_cast<const char*>(g_h0p) + idx * 16);
    }
    asm volatile("cp.async.commit_group;");

    // ===================== Phase 2: logits = H @ W^T + b ==================
    const int warp = tid >> 5;         // m-tile 0..15
    const int lane = tid & 31;
    const int g  = lane >> 2;
    const int tg = lane & 3;

    const int rowIn16 = ((lane >> 4) << 3) + (lane & 7);
    const int halfoff = ((lane >> 3) & 1) * 16;
    const uint32_t lmOff = (uint32_t)(rowIn16 * WPITCH + halfoff);
    const uint32_t stsOff = (uint32_t)((tid >> 4) * WPITCH + (tid & 15) * 16);

#pragma unroll 1
    for (int i = 0; i < nch; i++) {
        const int buf = i & 1;
        const uint32_t wbase = smem_base + SMEM_W0 + (uint32_t)buf * WBUF;

        // Convert prefetched W_i regs -> e4m3 Wf8[buf]
        {
            uint4 v;
            v.x = pack_e4m3(wreg[0].x * SCL, wreg[0].y * SCL, wreg[0].z * SCL, wreg[0].w * SCL);
            v.y = pack_e4m3(wreg[1].x * SCL, wreg[1].y * SCL, wreg[1].z * SCL, wreg[1].w * SCL);
            v.z = pack_e4m3(wreg[2].x * SCL, wreg[2].y * SCL, wreg[2].z * SCL, wreg[2].w * SCL);
            v.w = pack_e4m3(wreg[3].x * SCL, wreg[3].y * SCL, wreg[3].z * SCL, wreg[3].w * SCL);
            asm volatile("st.shared.v4.b32 [%0], {%1,%2,%3,%4};"
                         :: "r"(wbase + stsOff), "r"(v.x), "r"(v.y), "r"(v.z), "r"(v.w));
        }

        // Prefetch W_{i+1} (overlaps this chunk's MMA loop)
        if (i + 1 < nch) {
            const float4* W4 = reinterpret_cast<const float4*>(
                W + (size_t)((bid + NBLK * (i + 1)) * 32 + (tid >> 4)) * HID +
                (tid & 15) * 16);
#pragma unroll
            for (int j = 0; j < 4; j++) wreg[j] = W4[j];
        }

        if (i == 0) asm volatile("cp.async.wait_group 0;");
        __syncthreads();

        float c[4][4];
#pragma unroll
        for (int nf = 0; nf < 4; nf++)
#pragma unroll
            for (int q = 0; q < 4; q++) c[nf][q] = 0.f;

        const uint32_t WB = wbase + lmOff;
#pragma unroll
        for (int ks = 0; ks < 8; ks++) {
            uint4 va = *reinterpret_cast<const uint4*>(
                smem + SMEM_A + (size_t)(warp * 8 + ks) * 512 + lane * 16);
            const uint32_t kb = (uint32_t)(ks * 32);
#pragma unroll
            for (int nfp = 0; nfp < 2; nfp++) {
                uint32_t b0r, b1r, b2r, b3r;
                ldsm_x4(b0r, b1r, b2r, b3r, WB + (uint32_t)(nfp * 16 * WPITCH) + kb);
                mma_e4m3(c[2 * nfp],     va.x, va.y, va.z, va.w, b0r, b1r);
                mma_e4m3(c[2 * nfp + 1], va.x, va.y, va.z, va.w, b2r, b3r);
            }
        }

        const int n_base = (bid + NBLK * i) * 32;
        const int r0 = warp * 16 + g;
#pragma unroll
        for (int nf = 0; nf < 4; nf++) {
            const int n = n_base + nf * 8 + tg * 2;
            const float2 bo = *reinterpret_cast<const float2*>(b_out + n);
            float2 v0 = make_float2(fmaf(c[nf][0], INVS, bo.x),
                                    fmaf(c[nf][1], INVS, bo.y));
            float2 v1 = make_float2(fmaf(c[nf][2], INVS, bo.x),
                                    fmaf(c[nf][3], INVS, bo.y));
            *reinterpret_cast<float2*>(out + (size_t)(r0    ) * NCLS + n) = v0;
            *reinterpret_cast<float2*>(out + (size_t)(r0 + 8) * NCLS + n) = v1;
        }
        // Buffer alternation + one sync per iteration makes cross-iteration
        // smem reuse race-free (a warp can be at most one iteration ahead).
    }
}

// ---------------------------------------------------------------------------
extern "C" void kernel_launch(void* const* d_in, const int* in_sizes, int n_in,
                              void* d_out, int out_size)
{
    const int*   X       = (const int*)  d_in[0];
    const float* C_table = (const float*)d_in[1];
    const float* U_i     = (const float*)d_in[2];
    const float* b_i     = (const float*)d_in[4];
    const float* U_c     = (const float*)d_in[8];
    const float* b_c     = (const float*)d_in[10];
    const float* U_o     = (const float*)d_in[11];
    const float* b_o     = (const float*)d_in[13];
    const float* W_w     = (const float*)d_in[26];
    const float* b_out   = (const float*)d_in[27];
    float* out = (float*)d_out;

    cudaFuncSetAttribute(fused_kernel,
                         cudaFuncAttributeMaxDynamicSharedMemorySize, SMEM_BYTES);

    fused_kernel<<<NBLK, 512, SMEM_BYTES>>>(X, C_table, U_i, b_i, U_c, b_c,
                                            U_o, b_o, W_w, b_out, out);
}